// round 9
// baseline (speedup 1.0000x reference)
#include <cuda_runtime.h>
#include <cuda_bf16.h>

// Shapes (fixed): B=2, N=2048, K=48, A=4
// X: (B,N,4,3) f32; edge_idx: (B,N,48) i32; C: (B,N) i32
// out: (B,N,48,192) f32
//
// R = Q*diag(s): Q orthonormal, s_y=||n_y||. Each thread (k,a) loads and
// Q^T-rotates its atom; partner atoms via width-8 shuffles (no LDS in pair
// loop). Each pair computed exactly once per k-row.
// Results staged in smem laid out as the output image but with 28-float
// chunks per (k,a): quarter-warp STS.128 banks 28a mod 32 all distinct ->
// conflict-free. Copy-out is a pure stride loop: LDS.128 + coalesced STG.128.

#define BB 2
#define NN 2048
#define KK 48
#define EPS 0.1f
#define THREADS 384
#define CH 28                 // floats per (k,a) chunk (24 data + 4 pad)
#define KROW (8 * CH)         // 224 floats per k row

__global__ __launch_bounds__(THREADS) void edge_orient_kernel(
    const float* __restrict__ X,
    const int*   __restrict__ E,
    const int*   __restrict__ C,
    float*       __restrict__ out)
{
    const int bn = blockIdx.x;
    const int b  = bn >> 11;          // / NN
    const int t  = threadIdx.x;

    __shared__ __align__(16) float sOut[KK * KROW];   // 43008 B
    __shared__ int   sJ[KK];
    __shared__ float sR[9];
    __shared__ float sS[3];

    const int* e_row = E + (size_t)bn * KK;

    // ---- phase 1: neighbor indices + frame ----
    if (t < KK) sJ[t] = e_row[t];
    if (t == 64) {
        const float* xr = X + (size_t)bn * 12;
        float Nx = xr[0], Ny = xr[1], Nz = xr[2];
        float Ax = xr[3], Ay = xr[4], Az = xr[5];
        float Cx = xr[6], Cy = xr[7], Cz = xr[8];

        float ux = Nx - Ax, uy = Ny - Ay, uz = Nz - Az;
        float invE = rsqrtf(ux*ux + uy*uy + uz*uz + EPS);
        float n1x = ux*invE, n1y = uy*invE, n1z = uz*invE;
        float n1n2 = n1x*n1x + n1y*n1y + n1z*n1z;
        float inv0 = rsqrtf(n1n2);
        float q1x = n1x*inv0, q1y = n1y*inv0, q1z = n1z*inv0;
        float s1  = n1n2 * inv0;

        float vx = Cx - Ax, vy = Cy - Ay, vz = Cz - Az;
        float invV = rsqrtf(vx*vx + vy*vy + vz*vz + EPS);
        vx *= invV; vy *= invV; vz *= invV;

        float c2x = n1y*vz - n1z*vy;
        float c2y = n1z*vx - n1x*vz;
        float c2z = n1x*vy - n1y*vx;
        invE = rsqrtf(c2x*c2x + c2y*c2y + c2z*c2z + EPS);
        float n2x = c2x*invE, n2y = c2y*invE, n2z = c2z*invE;
        float n2n2 = n2x*n2x + n2y*n2y + n2z*n2z;
        inv0 = rsqrtf(n2n2);
        float q2x = n2x*inv0, q2y = n2y*inv0, q2z = n2z*inv0;
        float s2  = n2n2 * inv0;

        float c3x = n1y*n2z - n1z*n2y;
        float c3y = n1z*n2x - n1x*n2z;
        float c3z = n1x*n2y - n1y*n2x;
        invE = rsqrtf(c3x*c3x + c3y*c3y + c3z*c3z + EPS);
        float n3x = c3x*invE, n3y = c3y*invE, n3z = c3z*invE;
        float n3n2 = n3x*n3x + n3y*n3y + n3z*n3z;
        inv0 = rsqrtf(n3n2);

        sR[0] = q1x;      sR[1] = q1y;      sR[2] = q1z;
        sR[3] = q2x;      sR[4] = q2y;      sR[5] = q2z;
        sR[6] = n3x*inv0; sR[7] = n3y*inv0; sR[8] = n3z*inv0;
        sS[0] = s1; sS[1] = s2; sS[2] = n3n2 * inv0;
    }
    __syncthreads();

    // ---- phase 2: thread (k, a) rotates its atom, shuffles partners,
    //      computes 8 pairs, stages 24 floats into sOut ----
    {
        const int k = t >> 3;
        const int a = t & 7;
        const int j = sJ[k];

        const float* src = (a < 4)
            ? (X + (size_t)bn * 12 + 3 * a)
            : (X + ((size_t)(b * NN + j)) * 12 + 3 * (a - 4));
        const float x = src[0], y = src[1], z = src[2];
        const float rx = x*sR[0] + y*sR[1] + z*sR[2];
        const float ry = x*sR[3] + y*sR[4] + z*sR[5];
        const float rz = x*sR[6] + y*sR[7] + z*sR[8];

        const float mk = ((C[bn] > 0) && (C[b * NN + j] > 0)) ? 1.0f : 0.0f;
        const float ms1 = mk * sS[0], ms2 = mk * sS[1], ms3 = mk * sS[2];

        float4* chunk = (float4*)&sOut[k * KROW + a * CH];

        float res[12];
#pragma unroll
        for (int bq = 0; bq < 8; bq++) {
            const float bx = __shfl_sync(0xffffffffu, rx, bq, 8);
            const float by = __shfl_sync(0xffffffffu, ry, bq, 8);
            const float bz = __shfl_sync(0xffffffffu, rz, bq, 8);
            const float dx = bx - rx, dy = by - ry, dz = bz - rz;
            const float inv = rsqrtf(dx*dx + dy*dy + dz*dz + EPS);
            const int o = (bq & 3) * 3;
            res[o + 0] = dx * inv * ms1;
            res[o + 1] = dy * inv * ms2;
            res[o + 2] = dz * inv * ms3;
            if ((bq & 3) == 3) {
                const int half = (bq >> 2) * 3;     // 0 or 3
                chunk[half + 0] = make_float4(res[0], res[1], res[2],  res[3]);
                chunk[half + 1] = make_float4(res[4], res[5], res[6],  res[7]);
                chunk[half + 2] = make_float4(res[8], res[9], res[10], res[11]);
            }
        }
    }
    __syncthreads();

    // ---- phase 3: copy-out. r = t%48 invariant; k = t/48 + 8q ----
    {
        const int k0 = t / 48;
        const int r  = t - k0 * 48;       // float4 index within k row
        const int g  = 4 * r;             // first float (0..188)
        const int a2 = g / 24;            // owner chunk (float4 never crosses)
        const int i2 = g - 24 * a2;

        const float* rp = &sOut[k0 * KROW + a2 * CH + i2];
        float* op = out + (size_t)bn * (KK * 192) + 4 * t;

#pragma unroll
        for (int q = 0; q < 6; q++) {
            const float4 v = *(const float4*)(rp + q * (8 * KROW));
            *(float4*)(op + q * 1536) = v;
        }
    }
}

extern "C" void kernel_launch(void* const* d_in, const int* in_sizes, int n_in,
                              void* d_out, int out_size) {
    const float* X = (const float*)d_in[0];
    const int*   E = (const int*)d_in[1];
    const int*   C = (const int*)d_in[2];
    float* out = (float*)d_out;

    edge_orient_kernel<<<BB * NN, THREADS>>>(X, E, C, out);
}

// round 10
// speedup vs baseline: 1.0517x; 1.0517x over previous
#include <cuda_runtime.h>
#include <cuda_bf16.h>

// Shapes (fixed): B=2, N=2048, K=48, A=4
// X: (B,N,4,3) f32; edge_idx: (B,N,48) i32; C: (B,N) i32
// out: (B,N,48,192) f32
//
// R = Q*diag(s): Q orthonormal, s_y=||n_y||. Atoms rotated once by Q^T
// (norm-preserving); per pair: diff + rsqrt + per-axis (mask*s_y).
//
// Thread t writes output float4 f = t + 384q (q=0..5): coalesced STG.128.
// r = t%48 loop-invariant -> pair indices fixed per thread. i-atoms (a<4)
// are k-invariant: preloaded to registers before the loop. j-atoms read
// from a compact smem row (4 float4 per k). Masks preloaded to 6 regs.

#define BB 2
#define NN 2048
#define KK 48
#define EPS 0.1f
#define THREADS 384

__global__ __launch_bounds__(THREADS) void edge_orient_kernel(
    const float* __restrict__ X,
    const int*   __restrict__ E,
    const int*   __restrict__ C,
    float*       __restrict__ out)
{
    const int bn = blockIdx.x;
    const int b  = bn >> 11;          // / NN
    const int t  = threadIdx.x;

    __shared__ __align__(16) float4 sJA[KK][4];   // rotated j-atoms
    __shared__ __align__(16) float4 sIA[4];       // rotated i-atoms (once)
    __shared__ float sM[KK];                      // mask per k
    __shared__ int   sJ[KK];
    __shared__ float sR[9];
    __shared__ float sS[3];

    const int* e_row = E + (size_t)bn * KK;

    // ---- phase 1: neighbor indices + frame ----
    if (t < KK) sJ[t] = e_row[t];
    if (t == 64) {
        const float* xr = X + (size_t)bn * 12;
        float Nx = xr[0], Ny = xr[1], Nz = xr[2];
        float Ax = xr[3], Ay = xr[4], Az = xr[5];
        float Cx = xr[6], Cy = xr[7], Cz = xr[8];

        float ux = Nx - Ax, uy = Ny - Ay, uz = Nz - Az;
        float invE = rsqrtf(ux*ux + uy*uy + uz*uz + EPS);
        float n1x = ux*invE, n1y = uy*invE, n1z = uz*invE;
        float n1n2 = n1x*n1x + n1y*n1y + n1z*n1z;
        float inv0 = rsqrtf(n1n2);
        float q1x = n1x*inv0, q1y = n1y*inv0, q1z = n1z*inv0;
        float s1  = n1n2 * inv0;

        float vx = Cx - Ax, vy = Cy - Ay, vz = Cz - Az;
        float invV = rsqrtf(vx*vx + vy*vy + vz*vz + EPS);
        vx *= invV; vy *= invV; vz *= invV;

        float c2x = n1y*vz - n1z*vy;
        float c2y = n1z*vx - n1x*vz;
        float c2z = n1x*vy - n1y*vx;
        invE = rsqrtf(c2x*c2x + c2y*c2y + c2z*c2z + EPS);
        float n2x = c2x*invE, n2y = c2y*invE, n2z = c2z*invE;
        float n2n2 = n2x*n2x + n2y*n2y + n2z*n2z;
        inv0 = rsqrtf(n2n2);
        float q2x = n2x*inv0, q2y = n2y*inv0, q2z = n2z*inv0;
        float s2  = n2n2 * inv0;

        float c3x = n1y*n2z - n1z*n2y;
        float c3y = n1z*n2x - n1x*n2z;
        float c3z = n1x*n2y - n1y*n2x;
        invE = rsqrtf(c3x*c3x + c3y*c3y + c3z*c3z + EPS);
        float n3x = c3x*invE, n3y = c3y*invE, n3z = c3z*invE;
        float n3n2 = n3x*n3x + n3y*n3y + n3z*n3z;
        inv0 = rsqrtf(n3n2);

        sR[0] = q1x;      sR[1] = q1y;      sR[2] = q1z;
        sR[3] = q2x;      sR[4] = q2y;      sR[5] = q2z;
        sR[6] = n3x*inv0; sR[7] = n3y*inv0; sR[8] = n3z*inv0;
        sS[0] = s1; sS[1] = s2; sS[2] = n3n2 * inv0;
    }
    __syncthreads();

    // ---- phase 2: rotate atoms into smem ----
    {
        const int k = t >> 3;
        const int a = t & 7;
        if (a >= 4) {
            // j-atom (a-4) of neighbor sJ[k]
            const int j = sJ[k];
            const float* src = X + ((size_t)(b * NN + j)) * 12 + 3 * (a - 4);
            const float x = src[0], y = src[1], z = src[2];
            sJA[k][a - 4] = make_float4(
                x*sR[0] + y*sR[1] + z*sR[2],
                x*sR[3] + y*sR[4] + z*sR[5],
                x*sR[6] + y*sR[7] + z*sR[8], 0.0f);
        } else if (k == 0) {
            // i-atom a, stored once
            const float* src = X + (size_t)bn * 12 + 3 * a;
            const float x = src[0], y = src[1], z = src[2];
            sIA[a] = make_float4(
                x*sR[0] + y*sR[1] + z*sR[2],
                x*sR[3] + y*sR[4] + z*sR[5],
                x*sR[6] + y*sR[7] + z*sR[8], 0.0f);
        }
        if (a == 0) {
            const int j = sJ[k];
            sM[k] = ((C[bn] > 0) && (C[b * NN + j] > 0)) ? 1.0f : 0.0f;
        }
    }
    __syncthreads();

    // ---- phase 3: outputs ----
    const int k0 = t / 48;
    const int r  = t - k0 * 48;       // loop-invariant
    const int fr = 4 * r;
    const int s0 = fr / 3;
    const int c0 = fr - 3 * s0;
    const int s1i = s0 + 1;

    const int a0 = s0  >> 3, b0 = s0  & 7;
    const int a1 = s1i >> 3, b1 = s1i & 7;

    const float s1 = sS[0], s2 = sS[1], s3 = sS[2];

    // preload i-atoms used by this thread (k-invariant); j-atoms read in loop
    const bool A0i = (a0 < 4), B0i = (b0 < 4), A1i = (a1 < 4), B1i = (b1 < 4);
    const float4 zero4 = make_float4(0.f, 0.f, 0.f, 0.f);
    const float4 A0c = A0i ? sIA[a0] : zero4;
    const float4 B0c = B0i ? sIA[b0] : zero4;
    const float4 A1c = A1i ? sIA[a1] : zero4;
    const float4 B1c = B1i ? sIA[b1] : zero4;

    // preload masks for the 6 k values
    float mks[6];
#pragma unroll
    for (int q = 0; q < 6; q++) mks[q] = sM[k0 + 8 * q];

    float4* op = (float4*)(out + (size_t)bn * (KK * 192)) + t;

#pragma unroll
    for (int q = 0; q < 6; q++) {
        const int k = k0 + 8 * q;
        const float4* jrow = sJA[k];

        const float4 A0 = A0i ? A0c : jrow[a0 - 4];
        const float4 B0 = B0i ? B0c : jrow[b0 - 4];
        const float4 A1 = A1i ? A1c : jrow[a1 - 4];
        const float4 B1 = B1i ? B1c : jrow[b1 - 4];
        const float mk = mks[q];

        float v0x, v0y, v0z, v1x, v1y, v1z;
        {
            const float dx = B0.x - A0.x;
            const float dy = B0.y - A0.y;
            const float dz = B0.z - A0.z;
            const float inv = rsqrtf(dx*dx + dy*dy + dz*dz + EPS) * mk;
            v0x = dx * inv * s1; v0y = dy * inv * s2; v0z = dz * inv * s3;
        }
        {
            const float dx = B1.x - A1.x;
            const float dy = B1.y - A1.y;
            const float dz = B1.z - A1.z;
            const float inv = rsqrtf(dx*dx + dy*dy + dz*dz + EPS) * mk;
            v1x = dx * inv * s1; v1y = dy * inv * s2; v1z = dz * inv * s3;
        }

        float4 o;
        if (c0 == 0)      { o.x = v0x; o.y = v0y; o.z = v0z; o.w = v1x; }
        else if (c0 == 1) { o.x = v0y; o.y = v0z; o.z = v1x; o.w = v1y; }
        else              { o.x = v0z; o.y = v1x; o.z = v1y; o.w = v1z; }
        *op = o;
        op += THREADS;
    }
}

extern "C" void kernel_launch(void* const* d_in, const int* in_sizes, int n_in,
                              void* d_out, int out_size) {
    const float* X = (const float*)d_in[0];
    const int*   E = (const int*)d_in[1];
    const int*   C = (const int*)d_in[2];
    float* out = (float*)d_out;

    edge_orient_kernel<<<BB * NN, THREADS>>>(X, E, C, out);
}

// round 13
// speedup vs baseline: 1.2299x; 1.1694x over previous
#include <cuda_runtime.h>
#include <cuda_bf16.h>

// Shapes (fixed): B=2, N=2048, K=48, A=4
// X: (B,N,4,3) f32; edge_idx: (B,N,48) i32; C: (B,N) i32
// out: (B,N,48,192) f32
//
// R = Q*diag(s): Q orthonormal (exact), s_y = ||n_y||. Then
// U_rot[y] = s_y * (Q^T d)[y] * rsqrt(||d||^2 + eps), with ||d|| preserved
// by the Q^T rotation. Atoms rotated once in staging; per pair:
// diff + rsqrt (mask folded) + per-axis scale.
//
// Thread t writes output float4 f = t + 384q (q=0..5): coalesced STG.128.
// 384 = 8*48 -> r = f%48 invariant across q. Unrolled loop indexes smem
// with compile-time offsets (base + q*KSTRIDE immediates): no pointer
// carries, minimal ALU.

#define BB 2
#define NN 2048
#define KK 48
#define EPS 0.1f
#define THREADS 384
#define ROWF 24
#define KSTRIDE (8 * ROWF)

__global__ __launch_bounds__(THREADS) void edge_orient_v12_kernel(
    const float* __restrict__ X,
    const int*   __restrict__ E,
    const int*   __restrict__ C,
    float*       __restrict__ out)
{
    const int bn = blockIdx.x;
    const int b  = bn >> 11;          // / NN
    const int t  = threadIdx.x;

    __shared__ __align__(16) float sA[KK * ROWF];  // Q^T-rotated coords
    __shared__ float sM[KK];
    __shared__ float sR[9];
    __shared__ float sS[3];

    const int* e_row = E + (size_t)bn * KK;

    // ---- phase 1: raw coords, masks, frame ----
    if (t < KK * 6) {
        const int k  = t / 6;
        const int qq = t - k * 6;
        if (qq < 3) {
            ((float4*)&sA[k * ROWF])[qq] = ((const float4*)(X + (size_t)bn * 12))[qq];
        } else {
            const int j = e_row[k];
            ((float4*)&sA[k * ROWF])[qq] =
                ((const float4*)(X + ((size_t)(b * NN + j)) * 12))[qq - 3];
        }
    }
    if (t >= 288 && t < 288 + KK) {
        const int k = t - 288;
        const int j = e_row[k];
        sM[k] = ((C[bn] > 0) && (C[b * NN + j] > 0)) ? 1.0f : 0.0f;
    }
    if (t == 336) {
        const float* xr = X + (size_t)bn * 12;
        float Nx = xr[0], Ny = xr[1], Nz = xr[2];
        float Ax = xr[3], Ay = xr[4], Az = xr[5];
        float Cx = xr[6], Cy = xr[7], Cz = xr[8];

        float ux = Nx - Ax, uy = Ny - Ay, uz = Nz - Az;
        float invE = rsqrtf(ux*ux + uy*uy + uz*uz + EPS);
        float n1x = ux*invE, n1y = uy*invE, n1z = uz*invE;
        float n1n2 = n1x*n1x + n1y*n1y + n1z*n1z;
        float inv0 = rsqrtf(n1n2);
        float q1x = n1x*inv0, q1y = n1y*inv0, q1z = n1z*inv0;
        float s1  = n1n2 * inv0;

        float vx = Cx - Ax, vy = Cy - Ay, vz = Cz - Az;
        float invV = rsqrtf(vx*vx + vy*vy + vz*vz + EPS);
        vx *= invV; vy *= invV; vz *= invV;

        float c2x = n1y*vz - n1z*vy;
        float c2y = n1z*vx - n1x*vz;
        float c2z = n1x*vy - n1y*vx;
        invE = rsqrtf(c2x*c2x + c2y*c2y + c2z*c2z + EPS);
        float n2x = c2x*invE, n2y = c2y*invE, n2z = c2z*invE;
        float n2n2 = n2x*n2x + n2y*n2y + n2z*n2z;
        inv0 = rsqrtf(n2n2);
        float q2x = n2x*inv0, q2y = n2y*inv0, q2z = n2z*inv0;
        float s2  = n2n2 * inv0;

        float c3x = n1y*n2z - n1z*n2y;
        float c3y = n1z*n2x - n1x*n2z;
        float c3z = n1x*n2y - n1y*n2x;
        invE = rsqrtf(c3x*c3x + c3y*c3y + c3z*c3z + EPS);
        float n3x = c3x*invE, n3y = c3y*invE, n3z = c3z*invE;
        float n3n2 = n3x*n3x + n3y*n3y + n3z*n3z;
        inv0 = rsqrtf(n3n2);

        sR[0] = q1x;      sR[1] = q1y;      sR[2] = q1z;
        sR[3] = q2x;      sR[4] = q2y;      sR[5] = q2z;
        sR[6] = n3x*inv0; sR[7] = n3y*inv0; sR[8] = n3z*inv0;
        sS[0] = s1; sS[1] = s2; sS[2] = n3n2 * inv0;
    }
    __syncthreads();

    const float q1x = sR[0], q1y = sR[1], q1z = sR[2];
    const float q2x = sR[3], q2y = sR[4], q2z = sR[5];
    const float q3x = sR[6], q3y = sR[7], q3z = sR[8];
    const float s1 = sS[0], s2 = sS[1], s3 = sS[2];

    // ---- phase 2: rotate all atoms with Q^T (norm-preserving) ----
    {
        const int k = t >> 3;
        const int a = (t & 7) * 3;
        float* p = &sA[k * ROWF + a];
        const float x = p[0], y = p[1], z = p[2];
        const float rx = x*q1x + y*q1y + z*q1z;
        const float ry = x*q2x + y*q2y + z*q2z;
        const float rz = x*q3x + y*q3y + z*q3z;
        __syncthreads();
        p[0] = rx; p[1] = ry; p[2] = rz;
    }
    __syncthreads();

    // ---- phase 3: outputs; all indices base + compile-time immediates ----
    const int k0 = t / 48;
    const int r  = t - k0 * 48;       // loop-invariant
    const int fr = 4 * r;
    const int s0 = fr / 3;
    const int c0 = fr - s0 * 3;
    const int s1i = s0 + 1;

    const int base = k0 * ROWF;
    const int a0 = base + (s0  >> 3) * 3, b0 = base + (s0  & 7) * 3;
    const int a1 = base + (s1i >> 3) * 3, b1 = base + (s1i & 7) * 3;

    float4* op = (float4*)(out + (size_t)bn * (KK * 192)) + t;

#pragma unroll
    for (int q = 0; q < 6; q++) {
        const int o = q * KSTRIDE;           // compile-time immediate
        const float mk = sM[k0 + 8 * q];     // 8*q is immediate

        float v0x, v0y, v0z, v1x, v1y, v1z;
        {
            const float dx = sA[b0 + o]     - sA[a0 + o];
            const float dy = sA[b0 + o + 1] - sA[a0 + o + 1];
            const float dz = sA[b0 + o + 2] - sA[a0 + o + 2];
            const float inv = rsqrtf(dx*dx + dy*dy + dz*dz + EPS) * mk;
            v0x = dx * inv * s1; v0y = dy * inv * s2; v0z = dz * inv * s3;
        }
        {
            const float dx = sA[b1 + o]     - sA[a1 + o];
            const float dy = sA[b1 + o + 1] - sA[a1 + o + 1];
            const float dz = sA[b1 + o + 2] - sA[a1 + o + 2];
            const float inv = rsqrtf(dx*dx + dy*dy + dz*dz + EPS) * mk;
            v1x = dx * inv * s1; v1y = dy * inv * s2; v1z = dz * inv * s3;
        }

        float4 ov;
        if (c0 == 0)      { ov.x = v0x; ov.y = v0y; ov.z = v0z; ov.w = v1x; }
        else if (c0 == 1) { ov.x = v0y; ov.y = v0z; ov.z = v1x; ov.w = v1y; }
        else              { ov.x = v0z; ov.y = v1x; ov.z = v1y; ov.w = v1z; }
        op[q * THREADS] = ov;                // immediate offset store
    }
}

extern "C" void kernel_launch(void* const* d_in, const int* in_sizes, int n_in,
                              void* d_out, int out_size) {
    const float* X = (const float*)d_in[0];
    const int*   E = (const int*)d_in[1];
    const int*   C = (const int*)d_in[2];
    float* out = (float*)d_out;

    edge_orient_v12_kernel<<<BB * NN, THREADS>>>(X, E, C, out);
}

// round 15
// speedup vs baseline: 1.3077x; 1.0633x over previous
#include <cuda_runtime.h>
#include <cuda_bf16.h>

// Shapes (fixed): B=2, N=2048, K=48, A=4
// X: (B,N,4,3) f32; edge_idx: (B,N,48) i32; C: (B,N) i32
// out: (B,N,48,192) f32
//
// R = Q*diag(s): Q orthonormal, s_y=||n_y||. Atoms rotated once by Q^T and
// PRE-MASKED (coords *= mk; mk in {0,1} so masked diff -> exactly 0 output).
// Per pair: diff + rsqrt + per-axis s_y.
//
// Phase 3: lane owns 4 consecutive pairs = 12 floats = 3 float4s (static
// component packing, no selection). Warp covers 2 k-rows per pass (2 passes).
// Results go through a per-warp scratch (STS.128 conflict-free: banks
// 12l mod 32 distinct), then coalesced LDS.128 + STG.128. __syncwarp only.

#define BB 2
#define NN 2048
#define KK 48
#define EPS 0.1f
#define THREADS 384
#define ROWF 24

__global__ __launch_bounds__(THREADS) void edge_orient_v14_kernel(
    const float* __restrict__ X,
    const int*   __restrict__ E,
    const int*   __restrict__ C,
    float*       __restrict__ out)
{
    const int bn   = blockIdx.x;
    const int b    = bn >> 11;        // / NN
    const int t    = threadIdx.x;
    const int w    = t >> 5;
    const int lane = t & 31;

    __shared__ __align__(16) float  sA[KK * ROWF];   // rotated+masked coords
    __shared__ __align__(16) float4 sScr[12][96];    // per-warp scratch (18.4KB)
    __shared__ int   sJ[KK];
    __shared__ float sR[9];
    __shared__ float sS[3];

    const int* e_row = E + (size_t)bn * KK;

    // ---- phase 1: raw coords + neighbor idx + frame ----
    if (t < KK) sJ[t] = e_row[t];
    if (t < KK * 6) {
        const int k  = t / 6;
        const int qq = t - k * 6;
        if (qq < 3) {
            ((float4*)&sA[k * ROWF])[qq] = ((const float4*)(X + (size_t)bn * 12))[qq];
        } else {
            const int j = e_row[k];
            ((float4*)&sA[k * ROWF])[qq] =
                ((const float4*)(X + ((size_t)(b * NN + j)) * 12))[qq - 3];
        }
    }
    if (t == 336) {
        const float* xr = X + (size_t)bn * 12;
        float Nx = xr[0], Ny = xr[1], Nz = xr[2];
        float Ax = xr[3], Ay = xr[4], Az = xr[5];
        float Cx = xr[6], Cy = xr[7], Cz = xr[8];

        float ux = Nx - Ax, uy = Ny - Ay, uz = Nz - Az;
        float invE = rsqrtf(ux*ux + uy*uy + uz*uz + EPS);
        float n1x = ux*invE, n1y = uy*invE, n1z = uz*invE;
        float n1n2 = n1x*n1x + n1y*n1y + n1z*n1z;
        float inv0 = rsqrtf(n1n2);
        float q1x = n1x*inv0, q1y = n1y*inv0, q1z = n1z*inv0;
        float s1  = n1n2 * inv0;

        float vx = Cx - Ax, vy = Cy - Ay, vz = Cz - Az;
        float invV = rsqrtf(vx*vx + vy*vy + vz*vz + EPS);
        vx *= invV; vy *= invV; vz *= invV;

        float c2x = n1y*vz - n1z*vy;
        float c2y = n1z*vx - n1x*vz;
        float c2z = n1x*vy - n1y*vx;
        invE = rsqrtf(c2x*c2x + c2y*c2y + c2z*c2z + EPS);
        float n2x = c2x*invE, n2y = c2y*invE, n2z = c2z*invE;
        float n2n2 = n2x*n2x + n2y*n2y + n2z*n2z;
        inv0 = rsqrtf(n2n2);
        float q2x = n2x*inv0, q2y = n2y*inv0, q2z = n2z*inv0;
        float s2  = n2n2 * inv0;

        float c3x = n1y*n2z - n1z*n2y;
        float c3y = n1z*n2x - n1x*n2z;
        float c3z = n1x*n2y - n1y*n2x;
        invE = rsqrtf(c3x*c3x + c3y*c3y + c3z*c3z + EPS);
        float n3x = c3x*invE, n3y = c3y*invE, n3z = c3z*invE;
        float n3n2 = n3x*n3x + n3y*n3y + n3z*n3z;
        inv0 = rsqrtf(n3n2);

        sR[0] = q1x;      sR[1] = q1y;      sR[2] = q1z;
        sR[3] = q2x;      sR[4] = q2y;      sR[5] = q2z;
        sR[6] = n3x*inv0; sR[7] = n3y*inv0; sR[8] = n3z*inv0;
        sS[0] = s1; sS[1] = s2; sS[2] = n3n2 * inv0;
    }
    __syncthreads();

    // ---- phase 2: rotate + mask all atoms in place ----
    {
        const int k = t >> 3;
        const int a = (t & 7) * 3;
        const int j = sJ[k];
        const float mk = ((C[bn] > 0) && (C[b * NN + j] > 0)) ? 1.0f : 0.0f;
        float* p = &sA[k * ROWF + a];
        const float x = p[0], y = p[1], z = p[2];
        const float rx = (x*sR[0] + y*sR[1] + z*sR[2]) * mk;
        const float ry = (x*sR[3] + y*sR[4] + z*sR[5]) * mk;
        const float rz = (x*sR[6] + y*sR[7] + z*sR[8]) * mk;
        __syncthreads();
        p[0] = rx; p[1] = ry; p[2] = rz;
    }
    __syncthreads();

    const float s1 = sS[0], s2 = sS[1], s3 = sS[2];

    // ---- phase 3: lane = 4 pairs = 3 float4s; warp = 2 k-rows per pass ----
    // lane constants: rowsel = lane>>4, a = (lane&15)>>1, bbase = 4*(lane&1)
    const int rowsel = lane >> 4;
    const int aIdx   = (lane & 15) >> 1;
    const int bBase  = (lane & 1) * 4;

    float4* scr = &sScr[w][0];
    float4* obase = (float4*)(out + (size_t)bn * (KK * 192));

#pragma unroll
    for (int pass = 0; pass < 2; pass++) {
        const int rp  = w + 12 * pass;        // row-pair 0..23
        const int row = 2 * rp + rowsel;      // this lane's k row

        const float* rbase = &sA[row * ROWF];
        const float ax = rbase[3 * aIdx + 0];
        const float ay = rbase[3 * aIdx + 1];
        const float az = rbase[3 * aIdx + 2];

        float v[12];
#pragma unroll
        for (int i = 0; i < 4; i++) {
            const float* pb = rbase + 3 * (bBase + i);
            const float dx = pb[0] - ax;
            const float dy = pb[1] - ay;
            const float dz = pb[2] - az;
            float nn = fmaf(dx, dx, EPS);
            nn = fmaf(dy, dy, nn);
            nn = fmaf(dz, dz, nn);
            const float inv = rsqrtf(nn);
            v[3*i + 0] = dx * inv * s1;
            v[3*i + 1] = dy * inv * s2;
            v[3*i + 2] = dz * inv * s3;
        }

        // static packing: 12 floats -> 3 float4s at scratch slots 3l..3l+2
        scr[3*lane + 0] = make_float4(v[0], v[1], v[2],  v[3]);
        scr[3*lane + 1] = make_float4(v[4], v[5], v[6],  v[7]);
        scr[3*lane + 2] = make_float4(v[8], v[9], v[10], v[11]);

        __syncwarp();

        // coalesced copy-out: 96 float4s = rows 2rp, 2rp+1
        float4* od = obase + rp * 96;
#pragma unroll
        for (int i = 0; i < 3; i++) {
            od[32*i + lane] = scr[32*i + lane];
        }

        __syncwarp();
    }
}

extern "C" void kernel_launch(void* const* d_in, const int* in_sizes, int n_in,
                              void* d_out, int out_size) {
    const float* X = (const float*)d_in[0];
    const int*   E = (const int*)d_in[1];
    const int*   C = (const int*)d_in[2];
    float* out = (float*)d_out;

    edge_orient_v14_kernel<<<BB * NN, THREADS>>>(X, E, C, out);
}